// round 8
// baseline (speedup 1.0000x reference)
#include <cuda_runtime.h>
#include <cstdint>
#include <math.h>

#define Bsz 64
#define Tsz 4096
#define Dsz 128
#define Hsz 256

// Scratch for the input projection xp = x @ Wx + bx : [B][T][H] fp32
__device__ float g_xp[(size_t)Bsz * Tsz * Hsz];

// ---------------- packed fp32x2 helpers (sm_103a) ----------------
__device__ __forceinline__ unsigned long long pack2(float a, float b) {
    unsigned long long r;
    asm("mov.b64 %0, {%1, %2};" : "=l"(r) : "f"(a), "f"(b));
    return r;
}
__device__ __forceinline__ void fma2(unsigned long long& d, unsigned long long a, unsigned long long b) {
    asm("fma.rn.f32x2 %0, %1, %2, %0;" : "+l"(d) : "l"(a), "l"(b));
}
__device__ __forceinline__ unsigned long long add2(unsigned long long a, unsigned long long b) {
    unsigned long long r;
    asm("add.rn.f32x2 %0, %1, %2;" : "=l"(r) : "l"(a), "l"(b));
    return r;
}
__device__ __forceinline__ float2 unpack2(unsigned long long p) {
    float2 v;
    asm("mov.b64 {%0, %1}, %2;" : "=f"(v.x), "=f"(v.y) : "l"(p));
    return v;
}

__device__ __forceinline__ void mbar_wait_parity(unsigned addr, unsigned phase) {
    asm volatile(
        "{\n"
        ".reg .pred P%=;\n"
        "LW%=:\n"
        "mbarrier.try_wait.parity.acquire.cluster.shared::cta.b64 P%=, [%0], %1, 0x989680;\n"
        "@P%= bra LD%=;\n"
        "bra LW%=;\n"
        "LD%=:\n"
        "}\n"
        :: "r"(addr), "r"(phase) : "memory");
}

// fast tanh: 1 - 2/(e^{2x}+1) via ex2.approx + rcp.approx (~1e-6 rel err).
__device__ __forceinline__ float tanh_fast(float s) {
    float e;
    asm("ex2.approx.f32 %0, %1;" : "=f"(e) : "f"(s * 2.8853900817779268f));
    float r;
    asm("rcp.approx.f32 %0, %1;" : "=f"(r) : "f"(e + 1.0f));
    return __fmaf_rn(-2.0f, r, 1.0f);
}

// =====================================================================
// Fused kernel: per-cluster xp prologue + recurrence.
//   64 clusters x 2 CTAs, 512 threads/CTA.
//   Prologue: CTA computes xp[b][:, colbase..colbase+128) = x[b]@Wx+bx
//     (own batch, own columns only -> no cross-CTA sync; __syncthreads
//     gives STG->LDG visibility within the CTA).
//   Recurrence: R6 structure — warp0 mbar wait + BAR, local/remote MAC
//     overlap, select-free butterfly, single 512B bulk from tid0.
// =====================================================================
__global__ void __cluster_dims__(2, 1, 1) __launch_bounds__(512, 1)
fused_rnn_kernel(const float* __restrict__ x,
                 const float* __restrict__ Wx,
                 const float* __restrict__ bx,
                 const float* __restrict__ Wh,
                 const float* __restrict__ bh,
                 float* __restrict__ out)
{
    extern __shared__ float dynsm[];               // 96KB: prologue xs+ws, then hbuf
    __shared__ __align__(8) unsigned long long mbar[2];

    const int tid  = threadIdx.x;
    const int lane = tid & 31;
    const int warp = tid >> 5;

    unsigned rank;
    asm("mov.u32 %0, %%cluster_ctarank;" : "=r"(rank));
    const int b = blockIdx.x >> 1;
    const int colbase = (int)rank * 128;

    // ---------------- Phase 1: xp prologue (own batch, own 128 cols) --------
    {
        float* xs = dynsm;              // [128 k][64 m]  (32KB)
        float* ws = dynsm + 128 * 64;   // [128 k][128 n] (64KB)

        // load Wx half once
        {
            const int k  = tid >> 2;
            const int nq = (tid & 3) * 32;
            const float4* src = (const float4*)(Wx + (size_t)k * Hsz + colbase + nq);
            float4* dst = (float4*)(ws + k * 128 + nq);
#pragma unroll
            for (int i = 0; i < 8; ++i) dst[i] = src[i];
        }

        const int im = tid >> 4, in = tid & 15;
        const int m0 = im * 2, n0 = in * 8;
        unsigned long long bxp[4];
#pragma unroll
        for (int j = 0; j < 4; ++j)
            bxp[j] = pack2(bx[colbase + n0 + 2 * j], bx[colbase + n0 + 2 * j + 1]);

        for (int tb = 0; tb < Tsz / 64; ++tb) {
            __syncthreads();    // xs reuse guard (first iter: also orders ws)
            {
                const int row = tid & 63;
                const int kq  = (tid >> 6) * 16;
                const float4* src = (const float4*)(
                    x + ((size_t)b * Tsz + tb * 64 + row) * Dsz + kq);
#pragma unroll
                for (int i = 0; i < 4; ++i) {
                    float4 v = src[i];
                    int k = kq + i * 4;
                    xs[(k + 0) * 64 + row] = v.x;
                    xs[(k + 1) * 64 + row] = v.y;
                    xs[(k + 2) * 64 + row] = v.z;
                    xs[(k + 3) * 64 + row] = v.w;
                }
            }
            __syncthreads();

            unsigned long long acc[2][4];
#pragma unroll
            for (int mi = 0; mi < 2; ++mi)
#pragma unroll
                for (int j = 0; j < 4; ++j) acc[mi][j] = 0ULL;

#pragma unroll 8
            for (int k = 0; k < 128; ++k) {
                float2 a2 = *(const float2*)&xs[k * 64 + m0];
                unsigned long long ad0 = pack2(a2.x, a2.x);
                unsigned long long ad1 = pack2(a2.y, a2.y);
                ulonglong2 b01 = *(const ulonglong2*)&ws[k * 128 + n0];
                ulonglong2 b23 = *(const ulonglong2*)&ws[k * 128 + n0 + 4];
                fma2(acc[0][0], ad0, b01.x);
                fma2(acc[0][1], ad0, b01.y);
                fma2(acc[0][2], ad0, b23.x);
                fma2(acc[0][3], ad0, b23.y);
                fma2(acc[1][0], ad1, b01.x);
                fma2(acc[1][1], ad1, b01.y);
                fma2(acc[1][2], ad1, b23.x);
                fma2(acc[1][3], ad1, b23.y);
            }

#pragma unroll
            for (int mi = 0; mi < 2; ++mi) {
                const size_t row_g = (size_t)b * Tsz + tb * 64 + m0 + mi;
                ulonglong2 o1, o2;
                o1.x = add2(acc[mi][0], bxp[0]);
                o1.y = add2(acc[mi][1], bxp[1]);
                o2.x = add2(acc[mi][2], bxp[2]);
                o2.y = add2(acc[mi][3], bxp[3]);
                *(ulonglong2*)&g_xp[row_g * Hsz + colbase + n0]     = o1;
                *(ulonglong2*)&g_xp[row_g * Hsz + colbase + n0 + 4] = o2;
            }
        }
    }
    __syncthreads();   // prologue done: this CTA's xp cols visible CTA-wide

    // ---------------- Phase 2: recurrence --------------------------------
    float* hb = dynsm;                 // [2][256] double-buffered h

    const int loc_base = colbase;
    const int kl = loc_base + 4 * lane;        // local k sliver
    const int kr = kl ^ 128;                   // remote k sliver
    const int cg_base = loc_base + warp * 8;   // warp's first column

    const int m = (lane >> 2) & 7;             // column-slot XOR key
    const int cg_f = cg_base + m;              // this lane's final column
    const bool fin = ((lane & 3) == 0);

    // Register-resident Wh (loaded AFTER prologue to limit live ranges):
    // slot c covers column cg_base + (c ^ m)
    unsigned long long wl[8][2], wr[8][2];
#pragma unroll
    for (int c = 0; c < 8; ++c) {
        const int cg = cg_base + (c ^ m);
        wl[c][0] = pack2(Wh[(size_t)(kl + 0) * Hsz + cg],
                         Wh[(size_t)(kl + 1) * Hsz + cg]);
        wl[c][1] = pack2(Wh[(size_t)(kl + 2) * Hsz + cg],
                         Wh[(size_t)(kl + 3) * Hsz + cg]);
        wr[c][0] = pack2(Wh[(size_t)(kr + 0) * Hsz + cg],
                         Wh[(size_t)(kr + 1) * Hsz + cg]);
        wr[c][1] = pack2(Wh[(size_t)(kr + 2) * Hsz + cg],
                         Wh[(size_t)(kr + 3) * Hsz + cg]);
    }

    // h0 = 0 in both buffers; init + pre-arm both barriers (512B each)
    for (int i = tid; i < 2 * Hsz; i += 512) hb[i] = 0.0f;
    const unsigned hb_s  = (unsigned)__cvta_generic_to_shared(hb);
    const unsigned bar_s = (unsigned)__cvta_generic_to_shared(mbar);
    if (tid == 0) {
        asm volatile("mbarrier.init.shared.b64 [%0], 1;" :: "r"(bar_s) : "memory");
        asm volatile("mbarrier.init.shared.b64 [%0], 1;" :: "r"(bar_s + 8) : "memory");
        asm volatile("mbarrier.arrive.expect_tx.shared.b64 _, [%0], 512;" :: "r"(bar_s) : "memory");
        asm volatile("mbarrier.arrive.expect_tx.shared.b64 _, [%0], 512;" :: "r"(bar_s + 8) : "memory");
    }
    __syncthreads();
    asm volatile("barrier.cluster.arrive.aligned;" ::: "memory");
    asm volatile("barrier.cluster.wait.aligned;" ::: "memory");

    const unsigned peer = rank ^ 1u;
    unsigned hb_peer, bar_peer;
    asm("mapa.shared::cluster.u32 %0, %1, %2;" : "=r"(hb_peer)  : "r"(hb_s),  "r"(peer));
    asm("mapa.shared::cluster.u32 %0, %1, %2;" : "=r"(bar_peer) : "r"(bar_s), "r"(peer));

    const float bhv = fin ? bh[cg_f] : 0.0f;
    const size_t xbase = ((size_t)b * Tsz) * Hsz + cg_f;

    // xp: 4-step-ahead register prefetch (finalizer lanes only)
    float xc[4] = {0, 0, 0, 0};
    if (fin) {
#pragma unroll
        for (int i = 0; i < 4; ++i) xc[i] = __ldg(&g_xp[xbase + (size_t)i * Hsz]);
    }

    unsigned ph0 = 0, ph1 = 0;

    for (int t0 = 0; t0 < Tsz; t0 += 4) {
        float xn[4] = {0, 0, 0, 0};
        if (fin && t0 + 4 < Tsz) {
#pragma unroll
            for (int i = 0; i < 4; ++i)
                xn[i] = __ldg(&g_xp[xbase + (size_t)(t0 + 4 + i) * Hsz]);
        }
#pragma unroll
        for (int u = 0; u < 4; ++u) {
            const int t  = t0 + u;
            const int p  = u & 1;
            const int np = p ^ 1;

            unsigned long long acc[8];
#pragma unroll
            for (int c = 0; c < 8; ++c) acc[c] = 0ULL;

            // local-half MAC — overlaps the peer bulk still in flight
            {
                ulonglong2 hv = *(const ulonglong2*)&hb[p * Hsz + kl];
#pragma unroll
                for (int c = 0; c < 8; ++c) {
                    fma2(acc[c], hv.x, wl[c][0]);
                    fma2(acc[c], hv.y, wl[c][1]);
                }
            }

            // ONLY warp 0 polls the mbar; others park on bar.sync which
            // cannot release until warp 0 (post-wait) arrives.
            if (t > 0) {
                if (warp == 0) {
                    const unsigned bs = bar_s + (unsigned)p * 8u;
                    if (p) { mbar_wait_parity(bs, ph1); ph1 ^= 1u; }
                    else   { mbar_wait_parity(bs, ph0); ph0 ^= 1u; }
                    if (tid == 0)
                        asm volatile("mbarrier.arrive.expect_tx.shared.b64 _, [%0], 512;"
                                     :: "r"(bs) : "memory");
                }
            }
            __syncthreads();   // peer's half of hb[p] now visible to all

            // remote-half MAC
            {
                ulonglong2 hv = *(const ulonglong2*)&hb[p * Hsz + kr];
#pragma unroll
                for (int c = 0; c < 8; ++c) {
                    fma2(acc[c], hv.x, wr[c][0]);
                    fma2(acc[c], hv.y, wr[c][1]);
                }
            }

            // scalarize: s[j] = partial for column cg_base + (j ^ m)
            float s[8];
#pragma unroll
            for (int c = 0; c < 8; ++c) {
                float2 v = unpack2(acc[c]);
                s[c] = v.x + v.y;
            }

            // select-free butterfly (col(slot j) = j ^ m)
            float t4[4];
#pragma unroll
            for (int j = 0; j < 4; ++j)
                t4[j] = s[j] + __shfl_xor_sync(0xFFFFFFFFu, s[j + 4], 16);
            float t2[2];
#pragma unroll
            for (int j = 0; j < 2; ++j)
                t2[j] = t4[j] + __shfl_xor_sync(0xFFFFFFFFu, t4[j + 2], 8);
            float sum = t2[0] + __shfl_xor_sync(0xFFFFFFFFu, t2[1], 4);
            sum += __shfl_xor_sync(0xFFFFFFFFu, sum, 2);
            sum += __shfl_xor_sync(0xFFFFFFFFu, sum, 1);

            float hn = 0.0f;
            if (fin) {
                hn = tanh_fast(sum + xc[u] + bhv);
                hb[np * Hsz + cg_f] = hn;          // own half of h(t+1)
            }
            __syncthreads();   // own half of buf np fully stored & visible

            if (tid == 0 && t + 1 < Tsz) {
                asm volatile("fence.proxy.async.shared::cta;" ::: "memory");
                const unsigned off = (unsigned)np * 1024u + (unsigned)rank * 512u;
                asm volatile(
                    "cp.async.bulk.shared::cluster.shared::cta.mbarrier::complete_tx::bytes "
                    "[%0], [%1], %2, [%3];"
                    :: "r"(hb_peer + off), "r"(hb_s + off), "r"(512u),
                       "r"(bar_peer + (unsigned)np * 8u)
                    : "memory");
            }

            // off-chain output write (after the send is issued)
            if (fin) out[xbase + (size_t)t * Hsz] = hn;
        }
        if (fin) {
#pragma unroll
            for (int i = 0; i < 4; ++i) xc[i] = xn[i];
        }
    }

    asm volatile("barrier.cluster.arrive.aligned;" ::: "memory");
    asm volatile("barrier.cluster.wait.aligned;" ::: "memory");
}

// =====================================================================
extern "C" void kernel_launch(void* const* d_in, const int* in_sizes, int n_in,
                              void* d_out, int out_size)
{
    const float* x  = (const float*)d_in[0];  // [64, 4096, 128]
    const float* Wx = (const float*)d_in[1];  // [128, 256]
    const float* bx = (const float*)d_in[2];  // [256]
    const float* Wh = (const float*)d_in[3];  // [256, 256]
    const float* bh = (const float*)d_in[4];  // [256]
    float* out = (float*)d_out;               // [64, 4096, 256]

    const int smem_bytes = (128 * 64 + 128 * 128) * 4;  // 96 KB
    cudaFuncSetAttribute(fused_rnn_kernel,
                         cudaFuncAttributeMaxDynamicSharedMemorySize, smem_bytes);

    fused_rnn_kernel<<<2 * Bsz, 512, smem_bytes>>>(x, Wx, bx, Wh, bh, out);
}

// round 9
// speedup vs baseline: 1.3059x; 1.3059x over previous
#include <cuda_runtime.h>
#include <cstdint>
#include <math.h>

#define Bsz 64
#define Tsz 4096
#define Dsz 128
#define Hsz 256

// Scratch for the input projection xp = x @ Wx + bx : [B][T][H] fp32
__device__ float g_xp[(size_t)Bsz * Tsz * Hsz];

// ---------------- packed fp32x2 helpers (sm_103a) ----------------
__device__ __forceinline__ unsigned long long pack2(float a, float b) {
    unsigned long long r;
    asm("mov.b64 %0, {%1, %2};" : "=l"(r) : "f"(a), "f"(b));
    return r;
}
__device__ __forceinline__ void fma2(unsigned long long& d, unsigned long long a, unsigned long long b) {
    asm("fma.rn.f32x2 %0, %1, %2, %0;" : "+l"(d) : "l"(a), "l"(b));
}
__device__ __forceinline__ unsigned long long add2(unsigned long long a, unsigned long long b) {
    unsigned long long r;
    asm("add.rn.f32x2 %0, %1, %2;" : "=l"(r) : "l"(a), "l"(b));
    return r;
}
__device__ __forceinline__ float2 unpack2(unsigned long long p) {
    float2 v;
    asm("mov.b64 {%0, %1}, %2;" : "=f"(v.x), "=f"(v.y) : "l"(p));
    return v;
}

__device__ __forceinline__ void mbar_wait_parity(unsigned addr, unsigned phase) {
    asm volatile(
        "{\n"
        ".reg .pred P%=;\n"
        "LW%=:\n"
        "mbarrier.try_wait.parity.acquire.cluster.shared::cta.b64 P%=, [%0], %1, 0x989680;\n"
        "@P%= bra LD%=;\n"
        "bra LW%=;\n"
        "LD%=:\n"
        "}\n"
        :: "r"(addr), "r"(phase) : "memory");
}

// fast tanh: 1 - 2/(e^{2x}+1) via ex2.approx + rcp.approx (~1e-6 rel err,
// validated R8: rel_err unchanged at 2.53e-7).
__device__ __forceinline__ float tanh_fast(float s) {
    float e;
    asm("ex2.approx.f32 %0, %1;" : "=f"(e) : "f"(s * 2.8853900817779268f));
    float r;
    asm("rcp.approx.f32 %0, %1;" : "=f"(r) : "f"(e + 1.0f));
    return __fmaf_rn(-2.0f, r, 1.0f);
}

// =====================================================================
// Kernel 1: xp = x @ Wx + bx   (R1-R6 version — proven, ~507us)
// =====================================================================
__global__ void __launch_bounds__(256, 2) xp_gemm_kernel(
    const float* __restrict__ x,
    const float* __restrict__ Wx,
    const float* __restrict__ bx)
{
    extern __shared__ float sm[];
    float* xs = sm;               // [128][128], k-major
    float* ws = sm + 128 * 128;   // [128][64]

    const int tid = threadIdx.x;
    const size_t row0 = (size_t)blockIdx.x * 128;
    const int n_off = blockIdx.y * 64;

    {
        const int row = tid & 127;
        const int kh  = (tid >> 7) * 64;
        const float4* src = (const float4*)(x + (row0 + row) * Dsz + kh);
#pragma unroll
        for (int i = 0; i < 16; ++i) {
            float4 v = src[i];
            int k = kh + i * 4;
            xs[(k + 0) * 128 + row] = v.x;
            xs[(k + 1) * 128 + row] = v.y;
            xs[(k + 2) * 128 + row] = v.z;
            xs[(k + 3) * 128 + row] = v.w;
        }
    }
    {
        const int k = tid >> 1;
        const int half = (tid & 1) * 32;
        const float4* src = (const float4*)(Wx + (size_t)k * Hsz + n_off + half);
        float4* dst = (float4*)(ws + k * 64 + half);
#pragma unroll
        for (int i = 0; i < 8; ++i) dst[i] = src[i];
    }
    __syncthreads();

    const int im = tid >> 4, in = tid & 15;
    const int m0 = im * 8, n0 = in * 4;

    unsigned long long acc[4][4];
#pragma unroll
    for (int i = 0; i < 4; ++i)
#pragma unroll
        for (int j = 0; j < 4; ++j) acc[i][j] = 0ULL;

#pragma unroll 8
    for (int k = 0; k < 128; ++k) {
        const ulonglong2* ap = (const ulonglong2*)(xs + k * 128 + m0);
        ulonglong2 av0 = ap[0];
        ulonglong2 av1 = ap[1];
        unsigned long long a[4] = {av0.x, av0.y, av1.x, av1.y};
        float4 bv = *(const float4*)(ws + k * 64 + n0);
        unsigned long long bd[4];
        bd[0] = pack2(bv.x, bv.x);
        bd[1] = pack2(bv.y, bv.y);
        bd[2] = pack2(bv.z, bv.z);
        bd[3] = pack2(bv.w, bv.w);
#pragma unroll
        for (int i = 0; i < 4; ++i)
#pragma unroll
            for (int j = 0; j < 4; ++j)
                fma2(acc[i][j], a[i], bd[j]);
    }

    float bxv[4];
#pragma unroll
    for (int j = 0; j < 4; ++j) bxv[j] = __ldg(&bx[n_off + n0 + j]);

#pragma unroll
    for (int i = 0; i < 4; ++i) {
        float4 o0, o1;
        float2 c0 = unpack2(acc[i][0]); o0.x = c0.x + bxv[0]; o1.x = c0.y + bxv[0];
        float2 c1 = unpack2(acc[i][1]); o0.y = c1.x + bxv[1]; o1.y = c1.y + bxv[1];
        float2 c2 = unpack2(acc[i][2]); o0.z = c2.x + bxv[2]; o1.z = c2.y + bxv[2];
        float2 c3 = unpack2(acc[i][3]); o0.w = c3.x + bxv[3]; o1.w = c3.y + bxv[3];
        size_t r0 = row0 + m0 + 2 * i;
        *(float4*)(g_xp + r0 * Hsz + n_off + n0)       = o0;
        *(float4*)(g_xp + (r0 + 1) * Hsz + n_off + n0) = o1;
    }
}

// =====================================================================
// Kernel 2: recurrence — column-pair layout, 3-round reduce.
//   64 clusters x 2 CTAs, 512 threads/CTA, 16 warps.
//   Lane (r = lane&3, q = lane>>2):
//     cols  c0 = rank*128 + 8*warp + 2r, c1 = c0+1   (adjacent pair)
//     k:    local  kl = rank*128 + 16*q .. +16
//           remote kr = kl ^ 128
//   Column sums live in 8 lanes {r+4q} -> reduce = xor 4,8,16 (3 rounds).
//   Finalizers = lanes 0..3 (q==0): 2 cols each -> float2 STS/STG/xp.
//   Exchange: R6-proven — warp0 mbar wait + BAR, single 512B bulk (tid0).
// =====================================================================
__global__ void __cluster_dims__(2, 1, 1) __launch_bounds__(512, 1)
rnn_kernel(const float* __restrict__ Wh,
           const float* __restrict__ bh,
           float* __restrict__ out)
{
    __shared__ __align__(16) float hbuf[2][Hsz];   // [buf][global k]
    __shared__ __align__(8) unsigned long long mbar[2];

    const int tid  = threadIdx.x;
    const int lane = tid & 31;
    const int warp = tid >> 5;
    const int r    = lane & 3;
    const int q    = lane >> 2;

    unsigned rank;
    asm("mov.u32 %0, %%cluster_ctarank;" : "=r"(rank));
    const int b = blockIdx.x >> 1;

    const int loc_base = (int)rank * 128;
    const int kl = loc_base + 16 * q;          // local 16-k sliver
    const int kr = kl ^ 128;                   // remote 16-k sliver
    const int c0 = loc_base + warp * 8 + 2 * r;  // this lane's column pair
    const bool fin = (q == 0);

    // Register-resident Wh: 2 cols x (16 local + 16 remote) k = 32 f32x2
    unsigned long long wl0[8], wl1[8], wr0[8], wr1[8];
#pragma unroll
    for (int j = 0; j < 8; ++j) {
        const int k0l = kl + 2 * j;
        const int k0r = kr + 2 * j;
        wl0[j] = pack2(__ldg(&Wh[(size_t)k0l * Hsz + c0]),
                       __ldg(&Wh[(size_t)(k0l + 1) * Hsz + c0]));
        wl1[j] = pack2(__ldg(&Wh[(size_t)k0l * Hsz + c0 + 1]),
                       __ldg(&Wh[(size_t)(k0l + 1) * Hsz + c0 + 1]));
        wr0[j] = pack2(__ldg(&Wh[(size_t)k0r * Hsz + c0]),
                       __ldg(&Wh[(size_t)(k0r + 1) * Hsz + c0]));
        wr1[j] = pack2(__ldg(&Wh[(size_t)k0r * Hsz + c0 + 1]),
                       __ldg(&Wh[(size_t)(k0r + 1) * Hsz + c0 + 1]));
    }

    // h0 = 0 in both buffers; init + pre-arm both barriers (512B each)
    for (int i = tid; i < 2 * Hsz; i += 512) ((float*)hbuf)[i] = 0.0f;
    const unsigned hb_s  = (unsigned)__cvta_generic_to_shared(hbuf);
    const unsigned bar_s = (unsigned)__cvta_generic_to_shared(mbar);
    if (tid == 0) {
        asm volatile("mbarrier.init.shared.b64 [%0], 1;" :: "r"(bar_s) : "memory");
        asm volatile("mbarrier.init.shared.b64 [%0], 1;" :: "r"(bar_s + 8) : "memory");
        asm volatile("mbarrier.arrive.expect_tx.shared.b64 _, [%0], 512;" :: "r"(bar_s) : "memory");
        asm volatile("mbarrier.arrive.expect_tx.shared.b64 _, [%0], 512;" :: "r"(bar_s + 8) : "memory");
    }
    __syncthreads();
    asm volatile("barrier.cluster.arrive.aligned;" ::: "memory");
    asm volatile("barrier.cluster.wait.aligned;" ::: "memory");

    const unsigned peer = rank ^ 1u;
    unsigned hb_peer, bar_peer;
    asm("mapa.shared::cluster.u32 %0, %1, %2;" : "=r"(hb_peer)  : "r"(hb_s),  "r"(peer));
    asm("mapa.shared::cluster.u32 %0, %1, %2;" : "=r"(bar_peer) : "r"(bar_s), "r"(peer));

    float2 bhv = make_float2(0.0f, 0.0f);
    if (fin) bhv = *(const float2*)&bh[c0];
    const size_t xbase = ((size_t)b * Tsz) * Hsz + c0;

    // xp: 4-step-ahead register prefetch (finalizer lanes, float2)
    float2 xc[4];
#pragma unroll
    for (int i = 0; i < 4; ++i) xc[i] = make_float2(0.0f, 0.0f);
    if (fin) {
#pragma unroll
        for (int i = 0; i < 4; ++i)
            xc[i] = *(const float2*)__builtin_assume_aligned(&g_xp[xbase + (size_t)i * Hsz], 8);
    }

    unsigned ph0 = 0, ph1 = 0;

    for (int t0 = 0; t0 < Tsz; t0 += 4) {
        float2 xn[4];
#pragma unroll
        for (int i = 0; i < 4; ++i) xn[i] = make_float2(0.0f, 0.0f);
        if (fin && t0 + 4 < Tsz) {
#pragma unroll
            for (int i = 0; i < 4; ++i)
                xn[i] = *(const float2*)&g_xp[xbase + (size_t)(t0 + 4 + i) * Hsz];
        }
#pragma unroll
        for (int u = 0; u < 4; ++u) {
            const int t  = t0 + u;
            const int p  = u & 1;
            const int np = p ^ 1;

            unsigned long long a00 = 0, a01 = 0, a10 = 0, a11 = 0;

            // local-half MAC — overlaps the peer bulk still in flight
            {
                const ulonglong2* hp = (const ulonglong2*)&hbuf[p][kl];
#pragma unroll
                for (int i = 0; i < 4; ++i) {
                    ulonglong2 hv = hp[i];
                    fma2(a00, hv.x, wl0[2 * i]);
                    fma2(a01, hv.y, wl0[2 * i + 1]);
                    fma2(a10, hv.x, wl1[2 * i]);
                    fma2(a11, hv.y, wl1[2 * i + 1]);
                }
            }

            // ONLY warp 0 polls the mbar; others park on bar.sync which
            // cannot release until warp 0 (post-wait) arrives.
            if (t > 0) {
                if (warp == 0) {
                    const unsigned bs = bar_s + (unsigned)p * 8u;
                    if (p) { mbar_wait_parity(bs, ph1); ph1 ^= 1u; }
                    else   { mbar_wait_parity(bs, ph0); ph0 ^= 1u; }
                    if (tid == 0)
                        asm volatile("mbarrier.arrive.expect_tx.shared.b64 _, [%0], 512;"
                                     :: "r"(bs) : "memory");
                }
            }
            __syncthreads();   // peer's half of hbuf[p] now visible to all

            // remote-half MAC
            {
                const ulonglong2* hp = (const ulonglong2*)&hbuf[p][kr];
#pragma unroll
                for (int i = 0; i < 4; ++i) {
                    ulonglong2 hv = hp[i];
                    fma2(a00, hv.x, wr0[2 * i]);
                    fma2(a01, hv.y, wr0[2 * i + 1]);
                    fma2(a10, hv.x, wr1[2 * i]);
                    fma2(a11, hv.y, wr1[2 * i + 1]);
                }
            }

            // scalarize the two column partials
            float2 v0 = unpack2(add2(a00, a01));
            float2 v1 = unpack2(add2(a10, a11));
            float s0 = v0.x + v0.y;
            float s1 = v1.x + v1.y;

            // 3-round reduce over the 8 lanes {r+4q} holding this col pair
            s0 += __shfl_xor_sync(0xFFFFFFFFu, s0, 4);
            s1 += __shfl_xor_sync(0xFFFFFFFFu, s1, 4);
            s0 += __shfl_xor_sync(0xFFFFFFFFu, s0, 8);
            s1 += __shfl_xor_sync(0xFFFFFFFFu, s1, 8);
            s0 += __shfl_xor_sync(0xFFFFFFFFu, s0, 16);
            s1 += __shfl_xor_sync(0xFFFFFFFFu, s1, 16);

            float hn0 = 0.0f, hn1 = 0.0f;
            if (fin) {
                hn0 = tanh_fast(s0 + xc[u].x + bhv.x);
                hn1 = tanh_fast(s1 + xc[u].y + bhv.y);
                *(float2*)&hbuf[np][c0] = make_float2(hn0, hn1);  // own half
            }
            __syncthreads();   // own half of buf np fully stored & visible

            if (tid == 0 && t + 1 < Tsz) {
                asm volatile("fence.proxy.async.shared::cta;" ::: "memory");
                const unsigned off = (unsigned)np * 1024u + (unsigned)rank * 512u;
                asm volatile(
                    "cp.async.bulk.shared::cluster.shared::cta.mbarrier::complete_tx::bytes "
                    "[%0], [%1], %2, [%3];"
                    :: "r"(hb_peer + off), "r"(hb_s + off), "r"(512u),
                       "r"(bar_peer + (unsigned)np * 8u)
                    : "memory");
            }

            // off-chain output write (after the send is issued)
            if (fin)
                *(float2*)&out[xbase + (size_t)t * Hsz] = make_float2(hn0, hn1);
        }
        if (fin) {
#pragma unroll
            for (int i = 0; i < 4; ++i) xc[i] = xn[i];
        }
    }

    asm volatile("barrier.cluster.arrive.aligned;" ::: "memory");
    asm volatile("barrier.cluster.wait.aligned;" ::: "memory");
}

// =====================================================================
extern "C" void kernel_launch(void* const* d_in, const int* in_sizes, int n_in,
                              void* d_out, int out_size)
{
    const float* x  = (const float*)d_in[0];  // [64, 4096, 128]
    const float* Wx = (const float*)d_in[1];  // [128, 256]
    const float* bx = (const float*)d_in[2];  // [256]
    const float* Wh = (const float*)d_in[3];  // [256, 256]
    const float* bh = (const float*)d_in[4];  // [256]
    float* out = (float*)d_out;               // [64, 4096, 256]

    const int smem_bytes = (128 * 128 + 128 * 64) * 4;  // 96 KB
    cudaFuncSetAttribute(xp_gemm_kernel,
                         cudaFuncAttributeMaxDynamicSharedMemorySize, smem_bytes);

    dim3 ggrid((Bsz * Tsz) / 128, Hsz / 64, 1);
    xp_gemm_kernel<<<ggrid, 256, smem_bytes>>>(x, Wx, bx);

    rnn_kernel<<<2 * Bsz, 512>>>(Wh, bh, out);
}